// round 7
// baseline (speedup 1.0000x reference)
#include <cuda_runtime.h>
#include <cuda_fp16.h>
#include <cstdint>
#include <math.h>

// ============================================================================
// conv1 via mma.sync fp16 (HMMA), pure fp16 inputs. K' = 4608 (9 taps * 512).
// Padded-plane M: 26x26=676/plane, 130 planes (guards).
// R7: CTA tile 128M x 128N, 256 thr / 8 warps (4Mx2N), warp 32x64, K-chunk 64,
// 3-stage cp.async (96KB smem) -> 2 CTAs/SM, decoupled barrier domains.
// ============================================================================

#define NPLANE   676
#define KPRIME   512               // per-tap k' (pure fp16)
#define N_CHUNKS 72                // 9 taps * 8 chunks of 64
#define STAGE_B  32768             // A 16KB + B 16KB
#define CONV1_SMEM (3 * STAGE_B)

// ---------------- static device scratch ----------------
__device__ __half g_xs[130 * NPLANE * KPRIME];   // padded NHWC fp16 (~90MB)
__device__ __half g_wb[9 * 256 * KPRIME];        // weights [tap][n][k]
__device__ float g_scale[256];
__device__ float g_shift[256];
__device__ float g_x1[128 * 256 * 576];          // conv1 out, NCHW
__device__ float g_kmap[128 * 25 * 576];         // softmax maps

// ---------------- PTX helpers ----------------
__device__ __forceinline__ uint32_t smem_u32(const void* p) {
    uint32_t a;
    asm("{ .reg .u64 t; cvta.to.shared.u64 t, %1; cvt.u32.u64 %0, t; }" : "=r"(a) : "l"(p));
    return a;
}
#define CP_ASYNC16(dst, src) \
    asm volatile("cp.async.cg.shared.global [%0], [%1], 16;" :: "r"(dst), "l"(src) : "memory")
#define CP_COMMIT() asm volatile("cp.async.commit_group;" ::: "memory")
#define CP_WAIT(n)  asm volatile("cp.async.wait_group %0;" :: "n"(n) : "memory")

__device__ __forceinline__ void ldsm_x4(uint32_t* r, uint32_t addr) {
    asm volatile("ldmatrix.sync.aligned.m8n8.x4.shared.b16 {%0,%1,%2,%3}, [%4];"
                 : "=r"(r[0]), "=r"(r[1]), "=r"(r[2]), "=r"(r[3]) : "r"(addr));
}
__device__ __forceinline__ void mma_f16(float* c, const uint32_t* a, uint32_t b0, uint32_t b1) {
    asm volatile("mma.sync.aligned.m16n8k16.row.col.f32.f16.f16.f32 "
                 "{%0,%1,%2,%3}, {%4,%5,%6,%7}, {%8,%9}, {%0,%1,%2,%3};"
                 : "+f"(c[0]), "+f"(c[1]), "+f"(c[2]), "+f"(c[3])
                 : "r"(a[0]), "r"(a[1]), "r"(a[2]), "r"(a[3]), "r"(b0), "r"(b1));
}

// ---------------- prep: BN scale/shift fold ----------------
__global__ void snprep_kernel(const float* __restrict__ b1, const float* __restrict__ gam,
                              const float* __restrict__ bet, const float* __restrict__ mu,
                              const float* __restrict__ var) {
    int i = threadIdx.x;
    float inv = gam[i] * rsqrtf(var[i] + 1e-5f);
    g_scale[i] = inv;
    g_shift[i] = bet[i] + (b1[i] - mu[i]) * inv;
}

// ---------------- prep: weights -> fp16 [tap][n][k] ----------------
__global__ void wprep_kernel(const float* __restrict__ w1) {
    int idx = blockIdx.x * 256 + threadIdx.x;
    if (idx >= 9 * 256 * KPRIME) return;
    int kp = idx & 511;
    int n = (idx >> 9) & 255;
    int tap = idx >> 17;
    g_wb[idx] = __float2half(w1[((size_t)n * 512 + kp) * 9 + tap]);
}

// ---------------- prep: inputs -> padded NHWC fp16 ----------------
__global__ __launch_bounds__(256) void xprep_kernel(const float* __restrict__ src,
                                                    const float* __restrict__ det) {
    __shared__ float s[256][25];
    int blk = blockIdx.x;
    int p = blk / 26, yq = blk % 26;
    int t = threadIdx.x;
    __half* rowout = g_xs + (size_t)(p * NPLANE + yq * 26) * KPRIME;
    bool interior = (p >= 1 && p <= 128 && yq >= 1 && yq <= 24);
    if (!interior) {
        uint4 z = make_uint4(0, 0, 0, 0);
        uint4* o = (uint4*)rowout;
        for (int e = t; e < 26 * KPRIME / 8; e += 256) o[e] = z;
        return;
    }
    int b = p - 1, y = yq - 1;
    {
        uint4 z = make_uint4(0, 0, 0, 0);
        uint4* o0 = (uint4*)rowout;
        uint4* o1 = (uint4*)(rowout + (size_t)25 * KPRIME);
        for (int e = t; e < KPRIME / 8; e += 256) { o0[e] = z; o1[e] = z; }
    }
    for (int pass = 0; pass < 2; ++pass) {
        const float* in = pass ? det : src;
        for (int e = t; e < 256 * 24; e += 256) {
            int ch = e / 24, x = e - ch * 24;
            s[ch][x] = in[((size_t)b * 256 + ch) * 576 + y * 24 + x];
        }
        __syncthreads();
        int cb = pass * 256;
        for (int x = 0; x < 24; ++x) {
            __half* o = rowout + (size_t)(x + 1) * KPRIME;
            o[cb + t] = __float2half(s[t][x]);
        }
        __syncthreads();
    }
}

// ---------------- conv1: 128x128 CTA, 256 thr, warp 32x64, 2 CTA/SM ----------
__global__ __launch_bounds__(256, 2) void conv1_mma() {
    extern __shared__ __align__(1024) char smem_raw[];
    const uint32_t sbase = smem_u32(smem_raw);

    const int t = threadIdx.x;
    const int l = t & 31;
    const int w = t >> 5;                   // 0..7
    const int nbase = blockIdx.x * 128;     // N half
    const int m0 = blockIdx.y * 128;        // M tile

    // ---- staging precompute: row = t&127, half = t>>7, 4x16B chunks each ----
    const int srow = t & 127;
    const int shalf = t >> 7;
    uint32_t sdst[4];
#pragma unroll
    for (int g = 0; g < 4; g++) {
        int ch = shalf * 4 + g;
        sdst[g] = (uint32_t)srow * 128u + (uint32_t)((ch ^ (srow & 7)) * 16);
    }
    const size_t arow_noshift = (size_t)(NPLANE + m0 + srow);

    // ---- compute-side precompute ----
    const int wm = (w >> 1) * 32;            // warp M (0/32/64/96)
    const int wn = (w & 1) * 64;             // warp N (0/64)
    const uint32_t rsw = (uint32_t)(l & 7);
    const uint32_t kHi = (uint32_t)(l >> 4);
    uint32_t aRow[2], bRow[4];
#pragma unroll
    for (int mi = 0; mi < 2; mi++) aRow[mi] = (uint32_t)(wm + mi * 16 + (l & 15)) * 128u;
#pragma unroll
    for (int gi = 0; gi < 4; gi++) bRow[gi] = 16384u + (uint32_t)(wn + gi * 16 + (l & 15)) * 128u;

    float acc[2][8][4];
#pragma unroll
    for (int mi = 0; mi < 2; mi++)
#pragma unroll
        for (int ni = 0; ni < 8; ni++)
#pragma unroll
            for (int r = 0; r < 4; r++) acc[mi][ni][r] = 0.f;

    auto issue = [&](int c) {
        const int tap = c >> 3;                 // 8 chunks per tap
        const int kc = (c & 7) * 64;
        const int ty = tap / 3, tx = tap - ty * 3;
        const int shift = (ty - 1) * 26 + (tx - 1);
        const uint32_t St = sbase + (uint32_t)(c % 3) * STAGE_B;
        const __half* asrc = g_xs + (arow_noshift + shift) * KPRIME + kc + shalf * 32;
        const __half* bsrc = g_wb + ((size_t)(tap * 256 + nbase + srow)) * KPRIME
                           + kc + shalf * 32;
#pragma unroll
        for (int g = 0; g < 4; g++) {
            CP_ASYNC16(St + sdst[g], asrc + g * 8);
            CP_ASYNC16(St + 16384u + sdst[g], bsrc + g * 8);
        }
    };

    auto compute = [&](int c) {
        const uint32_t St = sbase + (uint32_t)(c % 3) * STAGE_B;
#pragma unroll
        for (int ks = 0; ks < 4; ks++) {
            const uint32_t off = (((uint32_t)(ks * 2) + kHi) ^ rsw) << 4;
            uint32_t a[2][4], b[4][4];
#pragma unroll
            for (int mi = 0; mi < 2; mi++) ldsm_x4(a[mi], St + aRow[mi] + off);
#pragma unroll
            for (int gi = 0; gi < 4; gi++) ldsm_x4(b[gi], St + bRow[gi] + off);
#pragma unroll
            for (int mi = 0; mi < 2; mi++)
#pragma unroll
                for (int gi = 0; gi < 4; gi++) {
                    mma_f16(acc[mi][gi * 2 + 0], a[mi], b[gi][0], b[gi][2]);
                    mma_f16(acc[mi][gi * 2 + 1], a[mi], b[gi][1], b[gi][3]);
                }
        }
    };

    issue(0); CP_COMMIT();
    issue(1); CP_COMMIT();
    for (int c = 0; c < N_CHUNKS; ++c) {
        if (c < N_CHUNKS - 1) { CP_WAIT(1); } else { CP_WAIT(0); }
        __syncthreads();
        if (c + 2 < N_CHUNKS) { issue(c + 2); CP_COMMIT(); }
        compute(c);
    }

    // ---- epilogue: BN + ReLU, drop padded rows, write g_x1 (NCHW) ----
    bool mvalid[4];
    float* mptr[4];
#pragma unroll
    for (int mi = 0; mi < 2; mi++)
#pragma unroll
        for (int h = 0; h < 2; h++) {
            int i = mi * 2 + h;
            int mg = m0 + wm + mi * 16 + (l >> 2) + h * 8;
            int plane = mg / 676;
            int pos = mg - plane * 676;
            int yq = pos / 26, xq = pos - yq * 26;
            mvalid[i] = (yq >= 1 && yq <= 24 && xq >= 1 && xq <= 24);
            mptr[i] = g_x1 + (size_t)plane * 147456 + (yq - 1) * 24 + (xq - 1);
        }
#pragma unroll
    for (int ni = 0; ni < 8; ni++) {
        int n0 = nbase + wn + (ni >> 1) * 16 + (ni & 1) * 8 + (l & 3) * 2;
        float sc0 = g_scale[n0], sh0 = g_shift[n0];
        float sc1 = g_scale[n0 + 1], sh1 = g_shift[n0 + 1];
#pragma unroll
        for (int mi = 0; mi < 2; mi++)
#pragma unroll
            for (int h = 0; h < 2; h++) {
                int i = mi * 2 + h;
                if (!mvalid[i]) continue;
                float v0 = fmaf(acc[mi][ni][h * 2 + 0], sc0, sh0);
                float v1 = fmaf(acc[mi][ni][h * 2 + 1], sc1, sh1);
                mptr[i][(size_t)n0 * 576] = fmaxf(v0, 0.f);
                mptr[i][(size_t)(n0 + 1) * 576] = fmaxf(v1, 0.f);
            }
    }
}

// ---------------- conv2 (1x1, 256->25) + bias + softmax ----------------
__global__ __launch_bounds__(128) void conv2_kernel(const float* __restrict__ w2,
                                                    const float* __restrict__ b2) {
    __shared__ float As[16][128];
    __shared__ float Bs[16][25];
    __shared__ float b2s[25];

    const int t = threadIdx.x;
    const int m = blockIdx.x * 128 + t;
    const int b = m / 576;
    const int pos = m - b * 576;
    const float* xp = g_x1 + (size_t)b * 147456 + pos;

    if (t < 25) b2s[t] = b2[t];

    float acc[25];
#pragma unroll
    for (int n = 0; n < 25; n++) acc[n] = 0.f;

    for (int kc = 0; kc < 256; kc += 16) {
#pragma unroll
        for (int kk = 0; kk < 16; kk++) As[kk][t] = xp[(size_t)(kc + kk) * 576];
        for (int e = t; e < 400; e += 128) {
            int k = e / 25;
            int n = e - k * 25;
            Bs[k][n] = w2[n * 256 + kc + k];
        }
        __syncthreads();
#pragma unroll
        for (int kk = 0; kk < 16; kk++) {
            float a = As[kk][t];
#pragma unroll
            for (int n = 0; n < 25; n++) acc[n] = fmaf(a, Bs[kk][n], acc[n]);
        }
        __syncthreads();
    }

    float mx = -1e30f;
#pragma unroll
    for (int n = 0; n < 25; n++) { acc[n] += b2s[n]; mx = fmaxf(mx, acc[n]); }
    float sum = 0.f;
#pragma unroll
    for (int n = 0; n < 25; n++) { acc[n] = __expf(acc[n] - mx); sum += acc[n]; }
    float inv = 1.f / sum;

    float* kp = g_kmap + (size_t)b * 14400 + pos;
#pragma unroll
    for (int n = 0; n < 25; n++) kp[(size_t)n * 576] = acc[n] * inv;
}

// ---------------- 25-tap propagation (channel-split grid) ----------------
#define CSPLIT 8
#define CPB    32

__global__ __launch_bounds__(192) void prop_kernel(const float* __restrict__ src,
                                                   float* __restrict__ out) {
    __shared__ float patch[2][336];

    const int t = threadIdx.x;
    const int blk = blockIdx.x;
    const int cs = blk & (CSPLIT - 1);
    const int brg = blk >> 3;
    const int b = brg / 3;
    const int rg = brg - b * 3;
    const int pos0 = rg * 192;
    const int y0 = rg * 8;
    const int c0 = cs * CPB;

    float pr[25];
    const float* kp = g_kmap + (size_t)b * 14400 + pos0 + t;
#pragma unroll
    for (int n = 0; n < 25; n++) pr[n] = kp[(size_t)n * 576];

    int off[2];
    bool val[2];
#pragma unroll
    for (int i = 0; i < 2; i++) {
        int e = t + i * 192;
        int ry = e / 28;
        int rx = e - ry * 28;
        int iy = y0 - 2 + ry;
        int ix = rx - 2;
        val[i] = (e < 336) && iy >= 0 && iy < 24 && ix >= 0 && ix < 24;
        off[i] = val[i] ? iy * 24 + ix : 0;
    }

    const float* sb = src + (size_t)b * 147456 + (size_t)c0 * 576;
    const int py = t / 24 + 2;
    const int px = t - (t / 24) * 24 + 2;
    const int pcenter = py * 28 + px;
    float* ob = out + (size_t)b * 147456 + (size_t)c0 * 576 + pos0 + t;

#pragma unroll
    for (int i = 0; i < 2; i++) {
        int e = t + i * 192;
        if (e < 336) patch[0][e] = val[i] ? sb[off[i]] : 0.f;
    }
    __syncthreads();

    for (int c = 0; c < CPB; ++c) {
        float nv[2];
        if (c + 1 < CPB) {
#pragma unroll
            for (int i = 0; i < 2; i++)
                nv[i] = val[i] ? sb[(size_t)(c + 1) * 576 + off[i]] : 0.f;
        }
        const float* pc = &patch[c & 1][0];
        float sum = 0.f;
#pragma unroll
        for (int o = 0; o < 25; o++) {
            int ddy = o / 5 - 2;
            int ddx = o - (o / 5) * 5 - 2;
            sum = fmaf(pc[pcenter + ddy * 28 + ddx], pr[o], sum);
        }
        ob[(size_t)c * 576] = sum;

        if (c + 1 < CPB) {
#pragma unroll
            for (int i = 0; i < 2; i++) {
                int e = t + i * 192;
                if (e < 336) patch[(c + 1) & 1][e] = nv[i];
            }
        }
        __syncthreads();
    }
}

// ---------------- launcher ----------------
extern "C" void kernel_launch(void* const* d_in, const int* in_sizes, int n_in,
                              void* d_out, int out_size) {
    const float* src = (const float*)d_in[0];
    const float* det = (const float*)d_in[1];
    const float* w1  = (const float*)d_in[2];
    const float* b1  = (const float*)d_in[3];
    const float* gam = (const float*)d_in[4];
    const float* bet = (const float*)d_in[5];
    const float* mu  = (const float*)d_in[6];
    const float* var = (const float*)d_in[7];
    const float* w2  = (const float*)d_in[8];
    const float* b2  = (const float*)d_in[9];
    float* out = (float*)d_out;

    cudaFuncSetAttribute(conv1_mma, cudaFuncAttributeMaxDynamicSharedMemorySize, CONV1_SMEM);

    snprep_kernel<<<1, 256>>>(b1, gam, bet, mu, var);
    wprep_kernel<<<(9 * 256 * KPRIME + 255) / 256, 256>>>(w1);
    xprep_kernel<<<130 * 26, 256>>>(src, det);

    dim3 g1(2, 676);                        // x = N half, y = M tile
    conv1_mma<<<g1, 256, CONV1_SMEM>>>();

    conv2_kernel<<<576, 128>>>(w2, b2);
    prop_kernel<<<128 * 3 * CSPLIT, 192>>>(src, out);
}

// round 8
// speedup vs baseline: 1.4193x; 1.4193x over previous
#include <cuda_runtime.h>
#include <cuda_fp16.h>
#include <cstdint>
#include <math.h>

// ============================================================================
// conv1 via mma.sync fp16 (HMMA), pure fp16 inputs. K' = 4608 (9 taps * 512).
// Padded-plane M: 26x26=676/plane, 130 planes (guards).
// R8: R6 base (CTA 128Mx256N, 512 thr, warp 32x64, K-chunk 64) +
//     4-stage cp.async (192KB smem) + register-fragment double buffering.
// ============================================================================

#define NPLANE   676
#define KPRIME   512               // per-tap k' (pure fp16)
#define N_CHUNKS 72                // 9 taps * 8 chunks of 64
#define STAGE_B  49152             // A 16KB + B 32KB
#define N_STAGE  4
#define CONV1_SMEM (N_STAGE * STAGE_B)

// ---------------- static device scratch ----------------
__device__ __half g_xs[130 * NPLANE * KPRIME];   // padded NHWC fp16 (~90MB)
__device__ __half g_wb[9 * 256 * KPRIME];        // weights [tap][n][k]
__device__ float g_scale[256];
__device__ float g_shift[256];
__device__ float g_x1[128 * 256 * 576];          // conv1 out, NCHW
__device__ float g_kmap[128 * 25 * 576];         // softmax maps

// ---------------- PTX helpers ----------------
__device__ __forceinline__ uint32_t smem_u32(const void* p) {
    uint32_t a;
    asm("{ .reg .u64 t; cvta.to.shared.u64 t, %1; cvt.u32.u64 %0, t; }" : "=r"(a) : "l"(p));
    return a;
}
#define CP_ASYNC16(dst, src) \
    asm volatile("cp.async.cg.shared.global [%0], [%1], 16;" :: "r"(dst), "l"(src) : "memory")
#define CP_COMMIT() asm volatile("cp.async.commit_group;" ::: "memory")
#define CP_WAIT(n)  asm volatile("cp.async.wait_group %0;" :: "n"(n) : "memory")

__device__ __forceinline__ void ldsm_x4(uint32_t* r, uint32_t addr) {
    asm volatile("ldmatrix.sync.aligned.m8n8.x4.shared.b16 {%0,%1,%2,%3}, [%4];"
                 : "=r"(r[0]), "=r"(r[1]), "=r"(r[2]), "=r"(r[3]) : "r"(addr));
}
__device__ __forceinline__ void mma_f16(float* c, const uint32_t* a, uint32_t b0, uint32_t b1) {
    asm volatile("mma.sync.aligned.m16n8k16.row.col.f32.f16.f16.f32 "
                 "{%0,%1,%2,%3}, {%4,%5,%6,%7}, {%8,%9}, {%0,%1,%2,%3};"
                 : "+f"(c[0]), "+f"(c[1]), "+f"(c[2]), "+f"(c[3])
                 : "r"(a[0]), "r"(a[1]), "r"(a[2]), "r"(a[3]), "r"(b0), "r"(b1));
}

// ---------------- prep: BN scale/shift fold ----------------
__global__ void snprep_kernel(const float* __restrict__ b1, const float* __restrict__ gam,
                              const float* __restrict__ bet, const float* __restrict__ mu,
                              const float* __restrict__ var) {
    int i = threadIdx.x;
    float inv = gam[i] * rsqrtf(var[i] + 1e-5f);
    g_scale[i] = inv;
    g_shift[i] = bet[i] + (b1[i] - mu[i]) * inv;
}

// ---------------- prep: weights -> fp16 [tap][n][k] ----------------
__global__ void wprep_kernel(const float* __restrict__ w1) {
    int idx = blockIdx.x * 256 + threadIdx.x;
    if (idx >= 9 * 256 * KPRIME) return;
    int kp = idx & 511;
    int n = (idx >> 9) & 255;
    int tap = idx >> 17;
    g_wb[idx] = __float2half(w1[((size_t)n * 512 + kp) * 9 + tap]);
}

// ---------------- prep: inputs -> padded NHWC fp16 ----------------
__global__ __launch_bounds__(256) void xprep_kernel(const float* __restrict__ src,
                                                    const float* __restrict__ det) {
    __shared__ float s[256][25];
    int blk = blockIdx.x;
    int p = blk / 26, yq = blk % 26;
    int t = threadIdx.x;
    __half* rowout = g_xs + (size_t)(p * NPLANE + yq * 26) * KPRIME;
    bool interior = (p >= 1 && p <= 128 && yq >= 1 && yq <= 24);
    if (!interior) {
        uint4 z = make_uint4(0, 0, 0, 0);
        uint4* o = (uint4*)rowout;
        for (int e = t; e < 26 * KPRIME / 8; e += 256) o[e] = z;
        return;
    }
    int b = p - 1, y = yq - 1;
    {
        uint4 z = make_uint4(0, 0, 0, 0);
        uint4* o0 = (uint4*)rowout;
        uint4* o1 = (uint4*)(rowout + (size_t)25 * KPRIME);
        for (int e = t; e < KPRIME / 8; e += 256) { o0[e] = z; o1[e] = z; }
    }
    for (int pass = 0; pass < 2; ++pass) {
        const float* in = pass ? det : src;
        for (int e = t; e < 256 * 24; e += 256) {
            int ch = e / 24, x = e - ch * 24;
            s[ch][x] = in[((size_t)b * 256 + ch) * 576 + y * 24 + x];
        }
        __syncthreads();
        int cb = pass * 256;
        for (int x = 0; x < 24; ++x) {
            __half* o = rowout + (size_t)(x + 1) * KPRIME;
            o[cb + t] = __float2half(s[t][x]);
        }
        __syncthreads();
    }
}

// ---------------- conv1: 128x256 CTA, 512 thr, warp 32x64, mma.sync fp16 ------
__global__ __launch_bounds__(512) void conv1_mma() {
    extern __shared__ __align__(1024) char smem_raw[];
    const uint32_t sbase = smem_u32(smem_raw);

    const int t = threadIdx.x;
    const int l = t & 31;
    const int w = t >> 5;                   // 0..15
    const int m0 = blockIdx.x * 128;

    // ---- staging precompute ----
    // A: 16KB/stage. row = t>>2, quarter q=t&3, 2x16B.
    const int arow = t >> 2;
    const int aq = t & 3;
    uint32_t sdstA[2];
#pragma unroll
    for (int g = 0; g < 2; g++) {
        int ch = aq * 2 + g;
        sdstA[g] = (uint32_t)arow * 128u + (uint32_t)((ch ^ (arow & 7)) * 16);
    }
    // B: 32KB/stage. row = t>>1, half bh=t&1, 4x16B.
    const int brow = t >> 1;
    const int bh = t & 1;
    uint32_t sdstB[4];
#pragma unroll
    for (int g = 0; g < 4; g++) {
        int ch = bh * 4 + g;
        sdstB[g] = 16384u + (uint32_t)brow * 128u + (uint32_t)((ch ^ (brow & 7)) * 16);
    }
    const size_t arow_noshift = (size_t)(NPLANE + m0 + arow);

    // ---- compute-side precompute ----
    const int wm = (w >> 2) * 32;            // warp M (0/32/64/96)
    const int wn = (w & 3) * 64;             // warp N (0/64/128/192)
    const uint32_t rsw = (uint32_t)(l & 7);
    const uint32_t kHi = (uint32_t)(l >> 4);
    uint32_t aRow[2], bRow[4];
#pragma unroll
    for (int mi = 0; mi < 2; mi++) aRow[mi] = (uint32_t)(wm + mi * 16 + (l & 15)) * 128u;
#pragma unroll
    for (int gi = 0; gi < 4; gi++) bRow[gi] = 16384u + (uint32_t)(wn + gi * 16 + (l & 15)) * 128u;

    float acc[2][8][4];
#pragma unroll
    for (int mi = 0; mi < 2; mi++)
#pragma unroll
        for (int ni = 0; ni < 8; ni++)
#pragma unroll
            for (int r = 0; r < 4; r++) acc[mi][ni][r] = 0.f;

    auto issue = [&](int c) {
        const int tap = c >> 3;                 // 8 chunks per tap
        const int kc = (c & 7) * 64;
        const int ty = tap / 3, tx = tap - ty * 3;
        const int shift = (ty - 1) * 26 + (tx - 1);
        const uint32_t St = sbase + (uint32_t)(c & (N_STAGE - 1)) * STAGE_B;
        const __half* asrc = g_xs + (arow_noshift + shift) * KPRIME + kc + aq * 16;
        const __half* bsrc = g_wb + ((size_t)(tap * 256 + brow)) * KPRIME + kc + bh * 32;
#pragma unroll
        for (int g = 0; g < 2; g++) CP_ASYNC16(St + sdstA[g], asrc + g * 8);
#pragma unroll
        for (int g = 0; g < 4; g++) CP_ASYNC16(St + sdstB[g], bsrc + g * 8);
    };

    // fragment double buffers
    uint32_t af[2][2][4], bf[2][4][4];

    auto load_frag = [&](uint32_t St, int ks, int buf) {
        const uint32_t off = (((uint32_t)(ks * 2) + kHi) ^ rsw) << 4;
#pragma unroll
        for (int mi = 0; mi < 2; mi++) ldsm_x4(af[buf][mi], St + aRow[mi] + off);
#pragma unroll
        for (int gi = 0; gi < 4; gi++) ldsm_x4(bf[buf][gi], St + bRow[gi] + off);
    };
    auto mma_frag = [&](int buf) {
#pragma unroll
        for (int mi = 0; mi < 2; mi++)
#pragma unroll
            for (int gi = 0; gi < 4; gi++) {
                mma_f16(acc[mi][gi * 2 + 0], af[buf][mi], bf[buf][gi][0], bf[buf][gi][2]);
                mma_f16(acc[mi][gi * 2 + 1], af[buf][mi], bf[buf][gi][1], bf[buf][gi][3]);
            }
    };

    auto compute = [&](int c) {
        const uint32_t St = sbase + (uint32_t)(c & (N_STAGE - 1)) * STAGE_B;
        load_frag(St, 0, 0);
#pragma unroll
        for (int ks = 0; ks < 4; ks++) {
            if (ks < 3) load_frag(St, ks + 1, (ks + 1) & 1);
            mma_frag(ks & 1);
        }
    };

    issue(0); CP_COMMIT();
    issue(1); CP_COMMIT();
    issue(2); CP_COMMIT();
    for (int c = 0; c < N_CHUNKS; ++c) {
        if (c <= N_CHUNKS - 3) { CP_WAIT(2); }
        else if (c == N_CHUNKS - 2) { CP_WAIT(1); }
        else { CP_WAIT(0); }
        __syncthreads();
        if (c + 3 < N_CHUNKS) { issue(c + 3); CP_COMMIT(); }
        compute(c);
    }

    // ---- epilogue: BN + ReLU, drop padded rows, write g_x1 (NCHW) ----
    bool mvalid[4];
    float* mptr[4];
#pragma unroll
    for (int mi = 0; mi < 2; mi++)
#pragma unroll
        for (int h = 0; h < 2; h++) {
            int i = mi * 2 + h;
            int mg = m0 + wm + mi * 16 + (l >> 2) + h * 8;
            int plane = mg / 676;
            int pos = mg - plane * 676;
            int yq = pos / 26, xq = pos - yq * 26;
            mvalid[i] = (yq >= 1 && yq <= 24 && xq >= 1 && xq <= 24);
            mptr[i] = g_x1 + (size_t)plane * 147456 + (yq - 1) * 24 + (xq - 1);
        }
#pragma unroll
    for (int ni = 0; ni < 8; ni++) {
        int n0 = wn + (ni >> 1) * 16 + (ni & 1) * 8 + (l & 3) * 2;
        float sc0 = g_scale[n0], sh0 = g_shift[n0];
        float sc1 = g_scale[n0 + 1], sh1 = g_shift[n0 + 1];
#pragma unroll
        for (int mi = 0; mi < 2; mi++)
#pragma unroll
            for (int h = 0; h < 2; h++) {
                int i = mi * 2 + h;
                if (!mvalid[i]) continue;
                float v0 = fmaf(acc[mi][ni][h * 2 + 0], sc0, sh0);
                float v1 = fmaf(acc[mi][ni][h * 2 + 1], sc1, sh1);
                mptr[i][(size_t)n0 * 576] = fmaxf(v0, 0.f);
                mptr[i][(size_t)(n0 + 1) * 576] = fmaxf(v1, 0.f);
            }
    }
}

// ---------------- conv2 (1x1, 256->25) + bias + softmax ----------------
__global__ __launch_bounds__(128) void conv2_kernel(const float* __restrict__ w2,
                                                    const float* __restrict__ b2) {
    __shared__ float As[16][128];
    __shared__ float Bs[16][25];
    __shared__ float b2s[25];

    const int t = threadIdx.x;
    const int m = blockIdx.x * 128 + t;
    const int b = m / 576;
    const int pos = m - b * 576;
    const float* xp = g_x1 + (size_t)b * 147456 + pos;

    if (t < 25) b2s[t] = b2[t];

    float acc[25];
#pragma unroll
    for (int n = 0; n < 25; n++) acc[n] = 0.f;

    for (int kc = 0; kc < 256; kc += 16) {
#pragma unroll
        for (int kk = 0; kk < 16; kk++) As[kk][t] = xp[(size_t)(kc + kk) * 576];
        for (int e = t; e < 400; e += 128) {
            int k = e / 25;
            int n = e - k * 25;
            Bs[k][n] = w2[n * 256 + kc + k];
        }
        __syncthreads();
#pragma unroll
        for (int kk = 0; kk < 16; kk++) {
            float a = As[kk][t];
#pragma unroll
            for (int n = 0; n < 25; n++) acc[n] = fmaf(a, Bs[kk][n], acc[n]);
        }
        __syncthreads();
    }

    float mx = -1e30f;
#pragma unroll
    for (int n = 0; n < 25; n++) { acc[n] += b2s[n]; mx = fmaxf(mx, acc[n]); }
    float sum = 0.f;
#pragma unroll
    for (int n = 0; n < 25; n++) { acc[n] = __expf(acc[n] - mx); sum += acc[n]; }
    float inv = 1.f / sum;

    float* kp = g_kmap + (size_t)b * 14400 + pos;
#pragma unroll
    for (int n = 0; n < 25; n++) kp[(size_t)n * 576] = acc[n] * inv;
}

// ---------------- 25-tap propagation (channel-split grid) ----------------
#define CSPLIT 8
#define CPB    32

__global__ __launch_bounds__(192) void prop_kernel(const float* __restrict__ src,
                                                   float* __restrict__ out) {
    __shared__ float patch[2][336];

    const int t = threadIdx.x;
    const int blk = blockIdx.x;
    const int cs = blk & (CSPLIT - 1);
    const int brg = blk >> 3;
    const int b = brg / 3;
    const int rg = brg - b * 3;
    const int pos0 = rg * 192;
    const int y0 = rg * 8;
    const int c0 = cs * CPB;

    float pr[25];
    const float* kp = g_kmap + (size_t)b * 14400 + pos0 + t;
#pragma unroll
    for (int n = 0; n < 25; n++) pr[n] = kp[(size_t)n * 576];

    int off[2];
    bool val[2];
#pragma unroll
    for (int i = 0; i < 2; i++) {
        int e = t + i * 192;
        int ry = e / 28;
        int rx = e - ry * 28;
        int iy = y0 - 2 + ry;
        int ix = rx - 2;
        val[i] = (e < 336) && iy >= 0 && iy < 24 && ix >= 0 && ix < 24;
        off[i] = val[i] ? iy * 24 + ix : 0;
    }

    const float* sb = src + (size_t)b * 147456 + (size_t)c0 * 576;
    const int py = t / 24 + 2;
    const int px = t - (t / 24) * 24 + 2;
    const int pcenter = py * 28 + px;
    float* ob = out + (size_t)b * 147456 + (size_t)c0 * 576 + pos0 + t;

#pragma unroll
    for (int i = 0; i < 2; i++) {
        int e = t + i * 192;
        if (e < 336) patch[0][e] = val[i] ? sb[off[i]] : 0.f;
    }
    __syncthreads();

    for (int c = 0; c < CPB; ++c) {
        float nv[2];
        if (c + 1 < CPB) {
#pragma unroll
            for (int i = 0; i < 2; i++)
                nv[i] = val[i] ? sb[(size_t)(c + 1) * 576 + off[i]] : 0.f;
        }
        const float* pc = &patch[c & 1][0];
        float sum = 0.f;
#pragma unroll
        for (int o = 0; o < 25; o++) {
            int ddy = o / 5 - 2;
            int ddx = o - (o / 5) * 5 - 2;
            sum = fmaf(pc[pcenter + ddy * 28 + ddx], pr[o], sum);
        }
        ob[(size_t)c * 576] = sum;

        if (c + 1 < CPB) {
#pragma unroll
            for (int i = 0; i < 2; i++) {
                int e = t + i * 192;
                if (e < 336) patch[(c + 1) & 1][e] = nv[i];
            }
        }
        __syncthreads();
    }
}

// ---------------- launcher ----------------
extern "C" void kernel_launch(void* const* d_in, const int* in_sizes, int n_in,
                              void* d_out, int out_size) {
    const float* src = (const float*)d_in[0];
    const float* det = (const float*)d_in[1];
    const float* w1  = (const float*)d_in[2];
    const float* b1  = (const float*)d_in[3];
    const float* gam = (const float*)d_in[4];
    const float* bet = (const float*)d_in[5];
    const float* mu  = (const float*)d_in[6];
    const float* var = (const float*)d_in[7];
    const float* w2  = (const float*)d_in[8];
    const float* b2  = (const float*)d_in[9];
    float* out = (float*)d_out;

    cudaFuncSetAttribute(conv1_mma, cudaFuncAttributeMaxDynamicSharedMemorySize, CONV1_SMEM);

    snprep_kernel<<<1, 256>>>(b1, gam, bet, mu, var);
    wprep_kernel<<<(9 * 256 * KPRIME + 255) / 256, 256>>>(w1);
    xprep_kernel<<<130 * 26, 256>>>(src, det);

    conv1_mma<<<676, 512, CONV1_SMEM>>>();

    conv2_kernel<<<576, 128>>>(w2, b2);
    prop_kernel<<<128 * 3 * CSPLIT, 192>>>(src, out);
}

// round 9
// speedup vs baseline: 1.6489x; 1.1618x over previous
#include <cuda_runtime.h>
#include <cuda_fp16.h>
#include <cstdint>
#include <math.h>

// ============================================================================
// conv1 via mma.sync fp16 (HMMA), pure fp16 inputs. K' = 4608 (9 taps * 512).
// Storage: padded 26x26 planes (zeros at borders) so tap shifts are linear.
// R9: M enumerates ONLY interior positions (M=73728, grid 576) -- per-thread
// row addresses point into padded planes; no wasted MMA rows, no epilogue mask.
// CTA 128Mx256N, 512 thr, warp 32x64, K-chunk 64, 4-stage cp.async, frag dbuf.
// ============================================================================

#define NPLANE   676
#define KPRIME   512               // per-tap k' (pure fp16)
#define N_CHUNKS 72                // 9 taps * 8 chunks of 64
#define STAGE_B  49152             // A 16KB + B 32KB
#define N_STAGE  4
#define CONV1_SMEM (N_STAGE * STAGE_B)

// ---------------- static device scratch ----------------
__device__ __half g_xs[130 * NPLANE * KPRIME];   // padded NHWC fp16 (~90MB)
__device__ __half g_wb[9 * 256 * KPRIME];        // weights [tap][n][k]
__device__ float g_scale[256];
__device__ float g_shift[256];
__device__ float g_x1[128 * 256 * 576];          // conv1 out, NCHW
__device__ float g_kmap[128 * 25 * 576];         // softmax maps

// ---------------- PTX helpers ----------------
__device__ __forceinline__ uint32_t smem_u32(const void* p) {
    uint32_t a;
    asm("{ .reg .u64 t; cvta.to.shared.u64 t, %1; cvt.u32.u64 %0, t; }" : "=r"(a) : "l"(p));
    return a;
}
#define CP_ASYNC16(dst, src) \
    asm volatile("cp.async.cg.shared.global [%0], [%1], 16;" :: "r"(dst), "l"(src) : "memory")
#define CP_COMMIT() asm volatile("cp.async.commit_group;" ::: "memory")
#define CP_WAIT(n)  asm volatile("cp.async.wait_group %0;" :: "n"(n) : "memory")

__device__ __forceinline__ void ldsm_x4(uint32_t* r, uint32_t addr) {
    asm volatile("ldmatrix.sync.aligned.m8n8.x4.shared.b16 {%0,%1,%2,%3}, [%4];"
                 : "=r"(r[0]), "=r"(r[1]), "=r"(r[2]), "=r"(r[3]) : "r"(addr));
}
__device__ __forceinline__ void mma_f16(float* c, const uint32_t* a, uint32_t b0, uint32_t b1) {
    asm volatile("mma.sync.aligned.m16n8k16.row.col.f32.f16.f16.f32 "
                 "{%0,%1,%2,%3}, {%4,%5,%6,%7}, {%8,%9}, {%0,%1,%2,%3};"
                 : "+f"(c[0]), "+f"(c[1]), "+f"(c[2]), "+f"(c[3])
                 : "r"(a[0]), "r"(a[1]), "r"(a[2]), "r"(a[3]), "r"(b0), "r"(b1));
}

// ---------------- prep: BN scale/shift fold ----------------
__global__ void snprep_kernel(const float* __restrict__ b1, const float* __restrict__ gam,
                              const float* __restrict__ bet, const float* __restrict__ mu,
                              const float* __restrict__ var) {
    int i = threadIdx.x;
    float inv = gam[i] * rsqrtf(var[i] + 1e-5f);
    g_scale[i] = inv;
    g_shift[i] = bet[i] + (b1[i] - mu[i]) * inv;
}

// ---------------- prep: weights -> fp16 [tap][n][k] ----------------
__global__ void wprep_kernel(const float* __restrict__ w1) {
    int idx = blockIdx.x * 256 + threadIdx.x;
    if (idx >= 9 * 256 * KPRIME) return;
    int kp = idx & 511;
    int n = (idx >> 9) & 255;
    int tap = idx >> 17;
    g_wb[idx] = __float2half(w1[((size_t)n * 512 + kp) * 9 + tap]);
}

// ---------------- prep: inputs -> padded NHWC fp16 ----------------
__global__ __launch_bounds__(256) void xprep_kernel(const float* __restrict__ src,
                                                    const float* __restrict__ det) {
    __shared__ float s[256][25];
    int blk = blockIdx.x;
    int p = blk / 26, yq = blk % 26;
    int t = threadIdx.x;
    __half* rowout = g_xs + (size_t)(p * NPLANE + yq * 26) * KPRIME;
    bool interior = (p >= 1 && p <= 128 && yq >= 1 && yq <= 24);
    if (!interior) {
        uint4 z = make_uint4(0, 0, 0, 0);
        uint4* o = (uint4*)rowout;
        for (int e = t; e < 26 * KPRIME / 8; e += 256) o[e] = z;
        return;
    }
    int b = p - 1, y = yq - 1;
    {
        uint4 z = make_uint4(0, 0, 0, 0);
        uint4* o0 = (uint4*)rowout;
        uint4* o1 = (uint4*)(rowout + (size_t)25 * KPRIME);
        for (int e = t; e < KPRIME / 8; e += 256) { o0[e] = z; o1[e] = z; }
    }
    for (int pass = 0; pass < 2; ++pass) {
        const float* in = pass ? det : src;
        for (int e = t; e < 256 * 24; e += 256) {
            int ch = e / 24, x = e - ch * 24;
            s[ch][x] = in[((size_t)b * 256 + ch) * 576 + y * 24 + x];
        }
        __syncthreads();
        int cb = pass * 256;
        for (int x = 0; x < 24; ++x) {
            __half* o = rowout + (size_t)(x + 1) * KPRIME;
            o[cb + t] = __float2half(s[t][x]);
        }
        __syncthreads();
    }
}

// ---------------- conv1: 128x256 CTA, interior-only M (73728), 512 thr -------
__global__ __launch_bounds__(512) void conv1_mma() {
    extern __shared__ __align__(1024) char smem_raw[];
    const uint32_t sbase = smem_u32(smem_raw);

    const int t = threadIdx.x;
    const int l = t & 31;
    const int w = t >> 5;                   // 0..15
    const int m0 = blockIdx.x * 128;

    // ---- A staging: row = t>>2 (interior m), quarter q=t&3, 2x16B ----
    const int arow = t >> 2;
    const int aq = t & 3;
    uint32_t sdstA[2];
#pragma unroll
    for (int g = 0; g < 2; g++) {
        int ch = aq * 2 + g;
        sdstA[g] = (uint32_t)arow * 128u + (uint32_t)((ch ^ (arow & 7)) * 16);
    }
    // interior m -> padded plane row address
    size_t abase;
    {
        const int mg = m0 + arow;
        const int b = mg / 576;
        const int pos = mg - b * 576;
        const int yy = pos / 24;
        const int xx = pos - yy * 24;
        abase = ((size_t)(b + 1) * NPLANE + (yy + 1) * 26 + (xx + 1)) * KPRIME
              + (size_t)aq * 16;
    }
    // B staging: row = t>>1, half bh=t&1, 4x16B
    const int brow = t >> 1;
    const int bh = t & 1;
    uint32_t sdstB[4];
#pragma unroll
    for (int g = 0; g < 4; g++) {
        int ch = bh * 4 + g;
        sdstB[g] = 16384u + (uint32_t)brow * 128u + (uint32_t)((ch ^ (brow & 7)) * 16);
    }

    // ---- compute-side precompute ----
    const int wm = (w >> 2) * 32;            // warp M (0/32/64/96)
    const int wn = (w & 3) * 64;             // warp N (0/64/128/192)
    const uint32_t rsw = (uint32_t)(l & 7);
    const uint32_t kHi = (uint32_t)(l >> 4);
    uint32_t aRow[2], bRow[4];
#pragma unroll
    for (int mi = 0; mi < 2; mi++) aRow[mi] = (uint32_t)(wm + mi * 16 + (l & 15)) * 128u;
#pragma unroll
    for (int gi = 0; gi < 4; gi++) bRow[gi] = 16384u + (uint32_t)(wn + gi * 16 + (l & 15)) * 128u;

    float acc[2][8][4];
#pragma unroll
    for (int mi = 0; mi < 2; mi++)
#pragma unroll
        for (int ni = 0; ni < 8; ni++)
#pragma unroll
            for (int r = 0; r < 4; r++) acc[mi][ni][r] = 0.f;

    auto issue = [&](int c) {
        const int tap = c >> 3;                 // 8 chunks per tap
        const int kc = (c & 7) * 64;
        const int ty = tap / 3, tx = tap - ty * 3;
        const int shift = (ty - 1) * 26 + (tx - 1);     // plane-row shift
        const uint32_t St = sbase + (uint32_t)(c & (N_STAGE - 1)) * STAGE_B;
        const __half* asrc = g_xs + abase + (ptrdiff_t)shift * KPRIME + kc;
        const __half* bsrc = g_wb + ((size_t)(tap * 256 + brow)) * KPRIME + kc + bh * 32;
#pragma unroll
        for (int g = 0; g < 2; g++) CP_ASYNC16(St + sdstA[g], asrc + g * 8);
#pragma unroll
        for (int g = 0; g < 4; g++) CP_ASYNC16(St + sdstB[g], bsrc + g * 8);
    };

    // fragment double buffers
    uint32_t af[2][2][4], bf[2][4][4];

    auto load_frag = [&](uint32_t St, int ks, int buf) {
        const uint32_t off = (((uint32_t)(ks * 2) + kHi) ^ rsw) << 4;
#pragma unroll
        for (int mi = 0; mi < 2; mi++) ldsm_x4(af[buf][mi], St + aRow[mi] + off);
#pragma unroll
        for (int gi = 0; gi < 4; gi++) ldsm_x4(bf[buf][gi], St + bRow[gi] + off);
    };
    auto mma_frag = [&](int buf) {
#pragma unroll
        for (int mi = 0; mi < 2; mi++)
#pragma unroll
            for (int gi = 0; gi < 4; gi++) {
                mma_f16(acc[mi][gi * 2 + 0], af[buf][mi], bf[buf][gi][0], bf[buf][gi][2]);
                mma_f16(acc[mi][gi * 2 + 1], af[buf][mi], bf[buf][gi][1], bf[buf][gi][3]);
            }
    };

    auto compute = [&](int c) {
        const uint32_t St = sbase + (uint32_t)(c & (N_STAGE - 1)) * STAGE_B;
        load_frag(St, 0, 0);
#pragma unroll
        for (int ks = 0; ks < 4; ks++) {
            if (ks < 3) load_frag(St, ks + 1, (ks + 1) & 1);
            mma_frag(ks & 1);
        }
    };

    issue(0); CP_COMMIT();
    issue(1); CP_COMMIT();
    issue(2); CP_COMMIT();
    for (int c = 0; c < N_CHUNKS; ++c) {
        if (c <= N_CHUNKS - 3) { CP_WAIT(2); }
        else if (c == N_CHUNKS - 2) { CP_WAIT(1); }
        else { CP_WAIT(0); }
        __syncthreads();
        if (c + 3 < N_CHUNKS) { issue(c + 3); CP_COMMIT(); }
        compute(c);
    }

    // ---- epilogue: BN + ReLU, all rows valid, write g_x1 (NCHW) ----
    float* mptr[4];
#pragma unroll
    for (int mi = 0; mi < 2; mi++)
#pragma unroll
        for (int h = 0; h < 2; h++) {
            int i = mi * 2 + h;
            int mg = m0 + wm + mi * 16 + (l >> 2) + h * 8;
            int b = mg / 576;
            int pos = mg - b * 576;
            mptr[i] = g_x1 + (size_t)b * 147456 + pos;
        }
#pragma unroll
    for (int ni = 0; ni < 8; ni++) {
        int n0 = wn + (ni >> 1) * 16 + (ni & 1) * 8 + (l & 3) * 2;
        float sc0 = g_scale[n0], sh0 = g_shift[n0];
        float sc1 = g_scale[n0 + 1], sh1 = g_shift[n0 + 1];
#pragma unroll
        for (int mi = 0; mi < 2; mi++)
#pragma unroll
            for (int h = 0; h < 2; h++) {
                int i = mi * 2 + h;
                float v0 = fmaf(acc[mi][ni][h * 2 + 0], sc0, sh0);
                float v1 = fmaf(acc[mi][ni][h * 2 + 1], sc1, sh1);
                mptr[i][(size_t)n0 * 576] = fmaxf(v0, 0.f);
                mptr[i][(size_t)(n0 + 1) * 576] = fmaxf(v1, 0.f);
            }
    }
}

// ---------------- conv2 (1x1, 256->25) + bias + softmax ----------------
__global__ __launch_bounds__(128) void conv2_kernel(const float* __restrict__ w2,
                                                    const float* __restrict__ b2) {
    __shared__ float As[16][128];
    __shared__ float Bs[16][25];
    __shared__ float b2s[25];

    const int t = threadIdx.x;
    const int m = blockIdx.x * 128 + t;
    const int b = m / 576;
    const int pos = m - b * 576;
    const float* xp = g_x1 + (size_t)b * 147456 + pos;

    if (t < 25) b2s[t] = b2[t];

    float acc[25];
#pragma unroll
    for (int n = 0; n < 25; n++) acc[n] = 0.f;

    for (int kc = 0; kc < 256; kc += 16) {
#pragma unroll
        for (int kk = 0; kk < 16; kk++) As[kk][t] = xp[(size_t)(kc + kk) * 576];
        for (int e = t; e < 400; e += 128) {
            int k = e / 25;
            int n = e - k * 25;
            Bs[k][n] = w2[n * 256 + kc + k];
        }
        __syncthreads();
#pragma unroll
        for (int kk = 0; kk < 16; kk++) {
            float a = As[kk][t];
#pragma unroll
            for (int n = 0; n < 25; n++) acc[n] = fmaf(a, Bs[kk][n], acc[n]);
        }
        __syncthreads();
    }

    float mx = -1e30f;
#pragma unroll
    for (int n = 0; n < 25; n++) { acc[n] += b2s[n]; mx = fmaxf(mx, acc[n]); }
    float sum = 0.f;
#pragma unroll
    for (int n = 0; n < 25; n++) { acc[n] = __expf(acc[n] - mx); sum += acc[n]; }
    float inv = 1.f / sum;

    float* kp = g_kmap + (size_t)b * 14400 + pos;
#pragma unroll
    for (int n = 0; n < 25; n++) kp[(size_t)n * 576] = acc[n] * inv;
}

// ---------------- 25-tap propagation (channel-split grid) ----------------
#define CSPLIT 8
#define CPB    32

__global__ __launch_bounds__(192) void prop_kernel(const float* __restrict__ src,
                                                   float* __restrict__ out) {
    __shared__ float patch[2][336];

    const int t = threadIdx.x;
    const int blk = blockIdx.x;
    const int cs = blk & (CSPLIT - 1);
    const int brg = blk >> 3;
    const int b = brg / 3;
    const int rg = brg - b * 3;
    const int pos0 = rg * 192;
    const int y0 = rg * 8;
    const int c0 = cs * CPB;

    float pr[25];
    const float* kp = g_kmap + (size_t)b * 14400 + pos0 + t;
#pragma unroll
    for (int n = 0; n < 25; n++) pr[n] = kp[(size_t)n * 576];

    int off[2];
    bool val[2];
#pragma unroll
    for (int i = 0; i < 2; i++) {
        int e = t + i * 192;
        int ry = e / 28;
        int rx = e - ry * 28;
        int iy = y0 - 2 + ry;
        int ix = rx - 2;
        val[i] = (e < 336) && iy >= 0 && iy < 24 && ix >= 0 && ix < 24;
        off[i] = val[i] ? iy * 24 + ix : 0;
    }

    const float* sb = src + (size_t)b * 147456 + (size_t)c0 * 576;
    const int py = t / 24 + 2;
    const int px = t - (t / 24) * 24 + 2;
    const int pcenter = py * 28 + px;
    float* ob = out + (size_t)b * 147456 + (size_t)c0 * 576 + pos0 + t;

#pragma unroll
    for (int i = 0; i < 2; i++) {
        int e = t + i * 192;
        if (e < 336) patch[0][e] = val[i] ? sb[off[i]] : 0.f;
    }
    __syncthreads();

    for (int c = 0; c < CPB; ++c) {
        float nv[2];
        if (c + 1 < CPB) {
#pragma unroll
            for (int i = 0; i < 2; i++)
                nv[i] = val[i] ? sb[(size_t)(c + 1) * 576 + off[i]] : 0.f;
        }
        const float* pc = &patch[c & 1][0];
        float sum = 0.f;
#pragma unroll
        for (int o = 0; o < 25; o++) {
            int ddy = o / 5 - 2;
            int ddx = o - (o / 5) * 5 - 2;
            sum = fmaf(pc[pcenter + ddy * 28 + ddx], pr[o], sum);
        }
        ob[(size_t)c * 576] = sum;

        if (c + 1 < CPB) {
#pragma unroll
            for (int i = 0; i < 2; i++) {
                int e = t + i * 192;
                if (e < 336) patch[(c + 1) & 1][e] = nv[i];
            }
        }
        __syncthreads();
    }
}

// ---------------- launcher ----------------
extern "C" void kernel_launch(void* const* d_in, const int* in_sizes, int n_in,
                              void* d_out, int out_size) {
    const float* src = (const float*)d_in[0];
    const float* det = (const float*)d_in[1];
    const float* w1  = (const float*)d_in[2];
    const float* b1  = (const float*)d_in[3];
    const float* gam = (const float*)d_in[4];
    const float* bet = (const float*)d_in[5];
    const float* mu  = (const float*)d_in[6];
    const float* var = (const float*)d_in[7];
    const float* w2  = (const float*)d_in[8];
    const float* b2  = (const float*)d_in[9];
    float* out = (float*)d_out;

    cudaFuncSetAttribute(conv1_mma, cudaFuncAttributeMaxDynamicSharedMemorySize, CONV1_SMEM);

    snprep_kernel<<<1, 256>>>(b1, gam, bet, mu, var);
    wprep_kernel<<<(9 * 256 * KPRIME + 255) / 256, 256>>>(w1);
    xprep_kernel<<<130 * 26, 256>>>(src, det);

    conv1_mma<<<576, 512, CONV1_SMEM>>>();   // 73728 / 128 interior M rows

    conv2_kernel<<<576, 128>>>(w2, b2);
    prop_kernel<<<128 * 3 * CSPLIT, 192>>>(src, out);
}

// round 10
// speedup vs baseline: 1.6873x; 1.0233x over previous
#include <cuda_runtime.h>
#include <cuda_fp16.h>
#include <cstdint>
#include <math.h>

// ============================================================================
// conv1 via mma.sync fp16 (HMMA), pure fp16 inputs. K' = 4608 (9 taps * 512).
// Storage: padded 26x26 planes (zeros at borders) so tap shifts are linear.
// R10: conv2(1x1,256->25)+bias+softmax FUSED into conv1 epilogue (x1 never
// touches DRAM; g_x1 deleted). CTA 128Mx256N, 512 thr, warp 32x64, K-chunk 64,
// 4-stage cp.async, fragment double buffering. M = interior-only 73728.
// ============================================================================

#define NPLANE   676
#define KPRIME   512               // per-tap k' (pure fp16)
#define N_CHUNKS 72                // 9 taps * 8 chunks of 64
#define STAGE_B  49152             // A 16KB + B 32KB
#define N_STAGE  4
#define CONV1_SMEM (N_STAGE * STAGE_B)   // 196608B; epilogue reuses this arena

// epilogue smem layout (floats, within the 192KB arena):
//   xs  [128][289]  at 0          (147968 B)  row stride 289 (=1 mod 32)
//   w2s [256][28]   at 36992      (28672 B)   transposed, [ch][n]
//   b2s [25]        at 44160
//   red [4][128][26] overlaid at 0 after xs dies (53248 B)
#define XS_OFF   0
#define W2S_OFF  36992
#define B2S_OFF  (36992 + 7168)

// ---------------- static device scratch ----------------
__device__ __half g_xs[130 * NPLANE * KPRIME];   // padded NHWC fp16 (~90MB)
__device__ __half g_wb[9 * 256 * KPRIME];        // weights [tap][n][k]
__device__ float g_scale[256];
__device__ float g_shift[256];
__device__ float g_kmap[128 * 25 * 576];         // softmax maps

// ---------------- PTX helpers ----------------
__device__ __forceinline__ uint32_t smem_u32(const void* p) {
    uint32_t a;
    asm("{ .reg .u64 t; cvta.to.shared.u64 t, %1; cvt.u32.u64 %0, t; }" : "=r"(a) : "l"(p));
    return a;
}
#define CP_ASYNC16(dst, src) \
    asm volatile("cp.async.cg.shared.global [%0], [%1], 16;" :: "r"(dst), "l"(src) : "memory")
#define CP_COMMIT() asm volatile("cp.async.commit_group;" ::: "memory")
#define CP_WAIT(n)  asm volatile("cp.async.wait_group %0;" :: "n"(n) : "memory")

__device__ __forceinline__ void ldsm_x4(uint32_t* r, uint32_t addr) {
    asm volatile("ldmatrix.sync.aligned.m8n8.x4.shared.b16 {%0,%1,%2,%3}, [%4];"
                 : "=r"(r[0]), "=r"(r[1]), "=r"(r[2]), "=r"(r[3]) : "r"(addr));
}
__device__ __forceinline__ void mma_f16(float* c, const uint32_t* a, uint32_t b0, uint32_t b1) {
    asm volatile("mma.sync.aligned.m16n8k16.row.col.f32.f16.f16.f32 "
                 "{%0,%1,%2,%3}, {%4,%5,%6,%7}, {%8,%9}, {%0,%1,%2,%3};"
                 : "+f"(c[0]), "+f"(c[1]), "+f"(c[2]), "+f"(c[3])
                 : "r"(a[0]), "r"(a[1]), "r"(a[2]), "r"(a[3]), "r"(b0), "r"(b1));
}

// ---------------- prep: BN scale/shift fold ----------------
__global__ void snprep_kernel(const float* __restrict__ b1, const float* __restrict__ gam,
                              const float* __restrict__ bet, const float* __restrict__ mu,
                              const float* __restrict__ var) {
    int i = threadIdx.x;
    float inv = gam[i] * rsqrtf(var[i] + 1e-5f);
    g_scale[i] = inv;
    g_shift[i] = bet[i] + (b1[i] - mu[i]) * inv;
}

// ---------------- prep: weights -> fp16 [tap][n][k] ----------------
__global__ void wprep_kernel(const float* __restrict__ w1) {
    int idx = blockIdx.x * 256 + threadIdx.x;
    if (idx >= 9 * 256 * KPRIME) return;
    int kp = idx & 511;
    int n = (idx >> 9) & 255;
    int tap = idx >> 17;
    g_wb[idx] = __float2half(w1[((size_t)n * 512 + kp) * 9 + tap]);
}

// ---------------- prep: inputs -> padded NHWC fp16 ----------------
__global__ __launch_bounds__(256) void xprep_kernel(const float* __restrict__ src,
                                                    const float* __restrict__ det) {
    __shared__ float s[256][25];
    int blk = blockIdx.x;
    int p = blk / 26, yq = blk % 26;
    int t = threadIdx.x;
    __half* rowout = g_xs + (size_t)(p * NPLANE + yq * 26) * KPRIME;
    bool interior = (p >= 1 && p <= 128 && yq >= 1 && yq <= 24);
    if (!interior) {
        uint4 z = make_uint4(0, 0, 0, 0);
        uint4* o = (uint4*)rowout;
        for (int e = t; e < 26 * KPRIME / 8; e += 256) o[e] = z;
        return;
    }
    int b = p - 1, y = yq - 1;
    {
        uint4 z = make_uint4(0, 0, 0, 0);
        uint4* o0 = (uint4*)rowout;
        uint4* o1 = (uint4*)(rowout + (size_t)25 * KPRIME);
        for (int e = t; e < KPRIME / 8; e += 256) { o0[e] = z; o1[e] = z; }
    }
    for (int pass = 0; pass < 2; ++pass) {
        const float* in = pass ? det : src;
        for (int e = t; e < 256 * 24; e += 256) {
            int ch = e / 24, x = e - ch * 24;
            s[ch][x] = in[((size_t)b * 256 + ch) * 576 + y * 24 + x];
        }
        __syncthreads();
        int cb = pass * 256;
        for (int x = 0; x < 24; ++x) {
            __half* o = rowout + (size_t)(x + 1) * KPRIME;
            o[cb + t] = __float2half(s[t][x]);
        }
        __syncthreads();
    }
}

// ---------------- conv1 + conv2 + softmax fused ----------------
__global__ __launch_bounds__(512) void conv1_mma(const float* __restrict__ w2,
                                                 const float* __restrict__ b2) {
    extern __shared__ __align__(1024) char smem_raw[];
    const uint32_t sbase = smem_u32(smem_raw);

    const int t = threadIdx.x;
    const int l = t & 31;
    const int w = t >> 5;                   // 0..15
    const int m0 = blockIdx.x * 128;

    // ---- A staging: row = t>>2 (interior m), quarter q=t&3, 2x16B ----
    const int arow = t >> 2;
    const int aq = t & 3;
    uint32_t sdstA[2];
#pragma unroll
    for (int g = 0; g < 2; g++) {
        int ch = aq * 2 + g;
        sdstA[g] = (uint32_t)arow * 128u + (uint32_t)((ch ^ (arow & 7)) * 16);
    }
    size_t abase;
    {
        const int mg = m0 + arow;
        const int b = mg / 576;
        const int pos = mg - b * 576;
        const int yy = pos / 24;
        const int xx = pos - yy * 24;
        abase = ((size_t)(b + 1) * NPLANE + (yy + 1) * 26 + (xx + 1)) * KPRIME
              + (size_t)aq * 16;
    }
    const int brow = t >> 1;
    const int bh = t & 1;
    uint32_t sdstB[4];
#pragma unroll
    for (int g = 0; g < 4; g++) {
        int ch = bh * 4 + g;
        sdstB[g] = 16384u + (uint32_t)brow * 128u + (uint32_t)((ch ^ (brow & 7)) * 16);
    }

    // ---- compute-side precompute ----
    const int wm = (w >> 2) * 32;            // warp M (0/32/64/96)
    const int wn = (w & 3) * 64;             // warp N (0/64/128/192)
    const uint32_t rsw = (uint32_t)(l & 7);
    const uint32_t kHi = (uint32_t)(l >> 4);
    uint32_t aRow[2], bRow[4];
#pragma unroll
    for (int mi = 0; mi < 2; mi++) aRow[mi] = (uint32_t)(wm + mi * 16 + (l & 15)) * 128u;
#pragma unroll
    for (int gi = 0; gi < 4; gi++) bRow[gi] = 16384u + (uint32_t)(wn + gi * 16 + (l & 15)) * 128u;

    float acc[2][8][4];
#pragma unroll
    for (int mi = 0; mi < 2; mi++)
#pragma unroll
        for (int ni = 0; ni < 8; ni++)
#pragma unroll
            for (int r = 0; r < 4; r++) acc[mi][ni][r] = 0.f;

    auto issue = [&](int c) {
        const int tap = c >> 3;
        const int kc = (c & 7) * 64;
        const int ty = tap / 3, tx = tap - ty * 3;
        const int shift = (ty - 1) * 26 + (tx - 1);
        const uint32_t St = sbase + (uint32_t)(c & (N_STAGE - 1)) * STAGE_B;
        const __half* asrc = g_xs + abase + (ptrdiff_t)shift * KPRIME + kc;
        const __half* bsrc = g_wb + ((size_t)(tap * 256 + brow)) * KPRIME + kc + bh * 32;
#pragma unroll
        for (int g = 0; g < 2; g++) CP_ASYNC16(St + sdstA[g], asrc + g * 8);
#pragma unroll
        for (int g = 0; g < 4; g++) CP_ASYNC16(St + sdstB[g], bsrc + g * 8);
    };

    uint32_t af[2][2][4], bf[2][4][4];
    auto load_frag = [&](uint32_t St, int ks, int buf) {
        const uint32_t off = (((uint32_t)(ks * 2) + kHi) ^ rsw) << 4;
#pragma unroll
        for (int mi = 0; mi < 2; mi++) ldsm_x4(af[buf][mi], St + aRow[mi] + off);
#pragma unroll
        for (int gi = 0; gi < 4; gi++) ldsm_x4(bf[buf][gi], St + bRow[gi] + off);
    };
    auto mma_frag = [&](int buf) {
#pragma unroll
        for (int mi = 0; mi < 2; mi++)
#pragma unroll
            for (int gi = 0; gi < 4; gi++) {
                mma_f16(acc[mi][gi * 2 + 0], af[buf][mi], bf[buf][gi][0], bf[buf][gi][2]);
                mma_f16(acc[mi][gi * 2 + 1], af[buf][mi], bf[buf][gi][1], bf[buf][gi][3]);
            }
    };
    auto compute = [&](int c) {
        const uint32_t St = sbase + (uint32_t)(c & (N_STAGE - 1)) * STAGE_B;
        load_frag(St, 0, 0);
#pragma unroll
        for (int ks = 0; ks < 4; ks++) {
            if (ks < 3) load_frag(St, ks + 1, (ks + 1) & 1);
            mma_frag(ks & 1);
        }
    };

    issue(0); CP_COMMIT();
    issue(1); CP_COMMIT();
    issue(2); CP_COMMIT();
    for (int c = 0; c < N_CHUNKS; ++c) {
        if (c <= N_CHUNKS - 3) { CP_WAIT(2); }
        else if (c == N_CHUNKS - 2) { CP_WAIT(1); }
        else { CP_WAIT(0); }
        __syncthreads();
        if (c + 3 < N_CHUNKS) { issue(c + 3); CP_COMMIT(); }
        compute(c);
    }

    // ================== fused epilogue: BN+ReLU -> conv2 -> softmax ==========
    __syncthreads();                          // all ldsm done; arena reusable
    float* smf = (float*)smem_raw;
    float* xs  = smf + XS_OFF;                // [128][289]
    float* w2s = smf + W2S_OFF;               // [256][28]  (transposed w2)
    float* b2s = smf + B2S_OFF;               // [25]

    // load w2 (transposed) + b2
    for (int e = t; e < 25 * 256; e += 512) {
        int n = e >> 8, ch = e & 255;
        w2s[ch * 28 + n] = w2[n * 256 + ch];
    }
    if (t < 25) b2s[t] = b2[t];

    // BN + ReLU, stage x1 into xs
#pragma unroll
    for (int ni = 0; ni < 8; ni++) {
        int n0 = wn + (ni >> 1) * 16 + (ni & 1) * 8 + (l & 3) * 2;
        float sc0 = g_scale[n0], sh0 = g_shift[n0];
        float sc1 = g_scale[n0 + 1], sh1 = g_shift[n0 + 1];
#pragma unroll
        for (int mi = 0; mi < 2; mi++)
#pragma unroll
            for (int h = 0; h < 2; h++) {
                int ml = wm + mi * 16 + (l >> 2) + h * 8;
                float v0 = fmaxf(fmaf(acc[mi][ni][h * 2 + 0], sc0, sh0), 0.f);
                float v1 = fmaxf(fmaf(acc[mi][ni][h * 2 + 1], sc1, sh1), 0.f);
                xs[ml * 289 + n0] = v0;
                xs[ml * 289 + n0 + 1] = v1;
            }
    }
    __syncthreads();

    // channel-quarter partial logits: warp w -> pg=w&3 (32 pos), cg=w>>2 (64 ch)
    const int pg = w & 3;
    const int cg = w >> 2;
    const int pos = pg * 32 + l;
    float lg[25];
#pragma unroll
    for (int n = 0; n < 25; n++) lg[n] = 0.f;
    {
        const float* xrow = xs + pos * 289 + cg * 64;
        const float* wrow = w2s + (cg * 64) * 28;
#pragma unroll 4
        for (int k = 0; k < 64; k++) {
            float xv = xrow[k];
            const float* wp = wrow + k * 28;
#pragma unroll
            for (int n = 0; n < 25; n++) lg[n] = fmaf(xv, wp[n], lg[n]);
        }
    }
    __syncthreads();                          // xs dead -> overlay red

    float* red = smf;                         // [4][128][26]
#pragma unroll
    for (int n = 0; n < 25; n++) red[(cg * 128 + pos) * 26 + n] = lg[n];
    __syncthreads();

    if (t < 128) {
        float v[25];
        float mx = -1e30f;
#pragma unroll
        for (int n = 0; n < 25; n++) {
            v[n] = red[t * 26 + n] + red[(128 + t) * 26 + n]
                 + red[(256 + t) * 26 + n] + red[(384 + t) * 26 + n] + b2s[n];
            mx = fmaxf(mx, v[n]);
        }
        float sum = 0.f;
#pragma unroll
        for (int n = 0; n < 25; n++) { v[n] = __expf(v[n] - mx); sum += v[n]; }
        float inv = 1.f / sum;
        int m = m0 + t;
        int b = m / 576;
        int pb = m - b * 576;
        float* kp = g_kmap + (size_t)b * 14400 + pb;
#pragma unroll
        for (int n = 0; n < 25; n++) kp[(size_t)n * 576] = v[n] * inv;
    }
}

// ---------------- 25-tap propagation (channel-split grid) ----------------
#define CSPLIT 8
#define CPB    32

__global__ __launch_bounds__(192) void prop_kernel(const float* __restrict__ src,
                                                   float* __restrict__ out) {
    __shared__ float patch[2][336];

    const int t = threadIdx.x;
    const int blk = blockIdx.x;
    const int cs = blk & (CSPLIT - 1);
    const int brg = blk >> 3;
    const int b = brg / 3;
    const int rg = brg - b * 3;
    const int pos0 = rg * 192;
    const int y0 = rg * 8;
    const int c0 = cs * CPB;

    float pr[25];
    const float* kp = g_kmap + (size_t)b * 14400 + pos0 + t;
#pragma unroll
    for (int n = 0; n < 25; n++) pr[n] = kp[(size_t)n * 576];

    int off[2];
    bool val[2];
#pragma unroll
    for (int i = 0; i < 2; i++) {
        int e = t + i * 192;
        int ry = e / 28;
        int rx = e - ry * 28;
        int iy = y0 - 2 + ry;
        int ix = rx - 2;
        val[i] = (e < 336) && iy >= 0 && iy < 24 && ix >= 0 && ix < 24;
        off[i] = val[i] ? iy * 24 + ix : 0;
    }

    const float* sb = src + (size_t)b * 147456 + (size_t)c0 * 576;
    const int py = t / 24 + 2;
    const int px = t - (t / 24) * 24 + 2;
    const int pcenter = py * 28 + px;
    float* ob = out + (size_t)b * 147456 + (size_t)c0 * 576 + pos0 + t;

#pragma unroll
    for (int i = 0; i < 2; i++) {
        int e = t + i * 192;
        if (e < 336) patch[0][e] = val[i] ? sb[off[i]] : 0.f;
    }
    __syncthreads();

    for (int c = 0; c < CPB; ++c) {
        float nv[2];
        if (c + 1 < CPB) {
#pragma unroll
            for (int i = 0; i < 2; i++)
                nv[i] = val[i] ? sb[(size_t)(c + 1) * 576 + off[i]] : 0.f;
        }
        const float* pc = &patch[c & 1][0];
        float sum = 0.f;
#pragma unroll
        for (int o = 0; o < 25; o++) {
            int ddy = o / 5 - 2;
            int ddx = o - (o / 5) * 5 - 2;
            sum = fmaf(pc[pcenter + ddy * 28 + ddx], pr[o], sum);
        }
        ob[(size_t)c * 576] = sum;

        if (c + 1 < CPB) {
#pragma unroll
            for (int i = 0; i < 2; i++) {
                int e = t + i * 192;
                if (e < 336) patch[(c + 1) & 1][e] = nv[i];
            }
        }
        __syncthreads();
    }
}

// ---------------- launcher ----------------
extern "C" void kernel_launch(void* const* d_in, const int* in_sizes, int n_in,
                              void* d_out, int out_size) {
    const float* src = (const float*)d_in[0];
    const float* det = (const float*)d_in[1];
    const float* w1  = (const float*)d_in[2];
    const float* b1  = (const float*)d_in[3];
    const float* gam = (const float*)d_in[4];
    const float* bet = (const float*)d_in[5];
    const float* mu  = (const float*)d_in[6];
    const float* var = (const float*)d_in[7];
    const float* w2  = (const float*)d_in[8];
    const float* b2  = (const float*)d_in[9];
    float* out = (float*)d_out;

    cudaFuncSetAttribute(conv1_mma, cudaFuncAttributeMaxDynamicSharedMemorySize, CONV1_SMEM);

    snprep_kernel<<<1, 256>>>(b1, gam, bet, mu, var);
    wprep_kernel<<<(9 * 256 * KPRIME + 255) / 256, 256>>>(w1);
    xprep_kernel<<<130 * 26, 256>>>(src, det);

    conv1_mma<<<576, 512, CONV1_SMEM>>>(w2, b2);   // conv1+BN+ReLU+conv2+softmax

    prop_kernel<<<128 * 3 * CSPLIT, 192>>>(src, out);
}

// round 11
// speedup vs baseline: 1.7988x; 1.0661x over previous
#include <cuda_runtime.h>
#include <cuda_fp16.h>
#include <cstdint>
#include <math.h>

// ============================================================================
// conv1 via mma.sync fp16 (HMMA), pure fp16 inputs. K' = 4608 (9 taps * 512).
// Storage: padded 26x26 planes (zeros at borders) so tap shifts are linear.
// R11: cross-chunk fragment rolling (no post-barrier ldsm ramp), vectorized
// fused conv2 epilogue (float4 LDS), guard planes dropped from xprep.
// CTA 128Mx256N, 512 thr, warp 32x64, K-chunk 64, 4-stage cp.async.
// ============================================================================

#define NPLANE   676
#define KPRIME   512               // per-tap k' (pure fp16)
#define N_CHUNKS 72                // 9 taps * 8 chunks of 64
#define STAGE_B  49152             // A 16KB + B 32KB
#define N_STAGE  4
#define CONV1_SMEM (N_STAGE * STAGE_B)   // 196608B; epilogue reuses this arena

// epilogue smem layout (floats):
//   xs  [128][292]  at 0         (stride 292: 16B-aligned rows, 4-bank lane skew)
//   w2s [256][28]   at 37376     (transposed, [ch][n], rows 112B = 16B-aligned)
//   b2s [25]        at 44544
//   red [4][128][26] overlaid at 0 after xs dies
#define XS_STRIDE 292
#define W2S_OFF   37376
#define B2S_OFF   44544

// ---------------- static device scratch ----------------
__device__ __half g_xs[130 * NPLANE * KPRIME];   // padded NHWC fp16 (~90MB)
__device__ __half g_wb[9 * 256 * KPRIME];        // weights [tap][n][k]
__device__ float g_scale[256];
__device__ float g_shift[256];
__device__ float g_kmap[128 * 25 * 576];         // softmax maps

// ---------------- PTX helpers ----------------
__device__ __forceinline__ uint32_t smem_u32(const void* p) {
    uint32_t a;
    asm("{ .reg .u64 t; cvta.to.shared.u64 t, %1; cvt.u32.u64 %0, t; }" : "=r"(a) : "l"(p));
    return a;
}
#define CP_ASYNC16(dst, src) \
    asm volatile("cp.async.cg.shared.global [%0], [%1], 16;" :: "r"(dst), "l"(src) : "memory")
#define CP_COMMIT() asm volatile("cp.async.commit_group;" ::: "memory")
#define CP_WAIT(n)  asm volatile("cp.async.wait_group %0;" :: "n"(n) : "memory")

__device__ __forceinline__ void ldsm_x4(uint32_t* r, uint32_t addr) {
    asm volatile("ldmatrix.sync.aligned.m8n8.x4.shared.b16 {%0,%1,%2,%3}, [%4];"
                 : "=r"(r[0]), "=r"(r[1]), "=r"(r[2]), "=r"(r[3]) : "r"(addr));
}
__device__ __forceinline__ void mma_f16(float* c, const uint32_t* a, uint32_t b0, uint32_t b1) {
    asm volatile("mma.sync.aligned.m16n8k16.row.col.f32.f16.f16.f32 "
                 "{%0,%1,%2,%3}, {%4,%5,%6,%7}, {%8,%9}, {%0,%1,%2,%3};"
                 : "+f"(c[0]), "+f"(c[1]), "+f"(c[2]), "+f"(c[3])
                 : "r"(a[0]), "r"(a[1]), "r"(a[2]), "r"(a[3]), "r"(b0), "r"(b1));
}

// ---------------- prep: BN scale/shift fold ----------------
__global__ void snprep_kernel(const float* __restrict__ b1, const float* __restrict__ gam,
                              const float* __restrict__ bet, const float* __restrict__ mu,
                              const float* __restrict__ var) {
    int i = threadIdx.x;
    float inv = gam[i] * rsqrtf(var[i] + 1e-5f);
    g_scale[i] = inv;
    g_shift[i] = bet[i] + (b1[i] - mu[i]) * inv;
}

// ---------------- prep: weights -> fp16 [tap][n][k] ----------------
__global__ void wprep_kernel(const float* __restrict__ w1) {
    int idx = blockIdx.x * 256 + threadIdx.x;
    if (idx >= 9 * 256 * KPRIME) return;
    int kp = idx & 511;
    int n = (idx >> 9) & 255;
    int tap = idx >> 17;
    g_wb[idx] = __float2half(w1[((size_t)n * 512 + kp) * 9 + tap]);
}

// ---------------- prep: inputs -> padded NHWC fp16 (planes 1..128 only) -----
__global__ __launch_bounds__(256) void xprep_kernel(const float* __restrict__ src,
                                                    const float* __restrict__ det) {
    __shared__ float s[256][25];
    int blk = blockIdx.x;
    int p = blk / 26 + 1;          // planes 1..128 (guards never read)
    int yq = blk % 26;
    int t = threadIdx.x;
    __half* rowout = g_xs + (size_t)(p * NPLANE + yq * 26) * KPRIME;
    if (yq < 1 || yq > 24) {       // pad rows
        uint4 z = make_uint4(0, 0, 0, 0);
        uint4* o = (uint4*)rowout;
        for (int e = t; e < 26 * KPRIME / 8; e += 256) o[e] = z;
        return;
    }
    int b = p - 1, y = yq - 1;
    {
        uint4 z = make_uint4(0, 0, 0, 0);
        uint4* o0 = (uint4*)rowout;
        uint4* o1 = (uint4*)(rowout + (size_t)25 * KPRIME);
        for (int e = t; e < KPRIME / 8; e += 256) { o0[e] = z; o1[e] = z; }
    }
    for (int pass = 0; pass < 2; ++pass) {
        const float* in = pass ? det : src;
        for (int e = t; e < 256 * 24; e += 256) {
            int ch = e / 24, x = e - ch * 24;
            s[ch][x] = in[((size_t)b * 256 + ch) * 576 + y * 24 + x];
        }
        __syncthreads();
        int cb = pass * 256;
        for (int x = 0; x < 24; ++x) {
            __half* o = rowout + (size_t)(x + 1) * KPRIME;
            o[cb + t] = __float2half(s[t][x]);
        }
        __syncthreads();
    }
}

// ---------------- conv1 + conv2 + softmax fused ----------------
__global__ __launch_bounds__(512) void conv1_mma(const float* __restrict__ w2,
                                                 const float* __restrict__ b2) {
    extern __shared__ __align__(1024) char smem_raw[];
    const uint32_t sbase = smem_u32(smem_raw);

    const int t = threadIdx.x;
    const int l = t & 31;
    const int w = t >> 5;                   // 0..15
    const int m0 = blockIdx.x * 128;

    // ---- A staging: row = t>>2 (interior m), quarter q=t&3, 2x16B ----
    const int arow = t >> 2;
    const int aq = t & 3;
    uint32_t sdstA[2];
#pragma unroll
    for (int g = 0; g < 2; g++) {
        int ch = aq * 2 + g;
        sdstA[g] = (uint32_t)arow * 128u + (uint32_t)((ch ^ (arow & 7)) * 16);
    }
    size_t abase;
    {
        const int mg = m0 + arow;
        const int b = mg / 576;
        const int pos = mg - b * 576;
        const int yy = pos / 24;
        const int xx = pos - yy * 24;
        abase = ((size_t)(b + 1) * NPLANE + (yy + 1) * 26 + (xx + 1)) * KPRIME
              + (size_t)aq * 16;
    }
    const int brow = t >> 1;
    const int bh = t & 1;
    uint32_t sdstB[4];
#pragma unroll
    for (int g = 0; g < 4; g++) {
        int ch = bh * 4 + g;
        sdstB[g] = 16384u + (uint32_t)brow * 128u + (uint32_t)((ch ^ (brow & 7)) * 16);
    }

    // ---- compute-side precompute ----
    const int wm = (w >> 2) * 32;            // warp M (0/32/64/96)
    const int wn = (w & 3) * 64;             // warp N (0/64/128/192)
    const uint32_t rsw = (uint32_t)(l & 7);
    const uint32_t kHi = (uint32_t)(l >> 4);
    uint32_t aRow[2], bRow[4];
#pragma unroll
    for (int mi = 0; mi < 2; mi++) aRow[mi] = (uint32_t)(wm + mi * 16 + (l & 15)) * 128u;
#pragma unroll
    for (int gi = 0; gi < 4; gi++) bRow[gi] = 16384u + (uint32_t)(wn + gi * 16 + (l & 15)) * 128u;

    float acc[2][8][4];
#pragma unroll
    for (int mi = 0; mi < 2; mi++)
#pragma unroll
        for (int ni = 0; ni < 8; ni++)
#pragma unroll
            for (int r = 0; r < 4; r++) acc[mi][ni][r] = 0.f;

    auto issue = [&](int c) {
        const int tap = c >> 3;
        const int kc = (c & 7) * 64;
        const int ty = tap / 3, tx = tap - ty * 3;
        const int shift = (ty - 1) * 26 + (tx - 1);
        const uint32_t St = sbase + (uint32_t)(c & (N_STAGE - 1)) * STAGE_B;
        const __half* asrc = g_xs + abase + (ptrdiff_t)shift * KPRIME + kc;
        const __half* bsrc = g_wb + ((size_t)(tap * 256 + brow)) * KPRIME + kc + bh * 32;
#pragma unroll
        for (int g = 0; g < 2; g++) CP_ASYNC16(St + sdstA[g], asrc + g * 8);
#pragma unroll
        for (int g = 0; g < 4; g++) CP_ASYNC16(St + sdstB[g], bsrc + g * 8);
    };

    uint32_t af[2][2][4], bf[2][4][4];
    auto load_frag = [&](uint32_t St, int ks, int buf) {
        const uint32_t off = (((uint32_t)(ks * 2) + kHi) ^ rsw) << 4;
#pragma unroll
        for (int mi = 0; mi < 2; mi++) ldsm_x4(af[buf][mi], St + aRow[mi] + off);
#pragma unroll
        for (int gi = 0; gi < 4; gi++) ldsm_x4(bf[buf][gi], St + bRow[gi] + off);
    };
    auto mma_frag = [&](int buf) {
#pragma unroll
        for (int mi = 0; mi < 2; mi++)
#pragma unroll
            for (int gi = 0; gi < 4; gi++) {
                mma_f16(acc[mi][gi * 2 + 0], af[buf][mi], bf[buf][gi][0], bf[buf][gi][2]);
                mma_f16(acc[mi][gi * 2 + 1], af[buf][mi], bf[buf][gi][1], bf[buf][gi][3]);
            }
    };

    issue(0); CP_COMMIT();
    issue(1); CP_COMMIT();
    issue(2); CP_COMMIT();
    for (int c = 0; c < N_CHUNKS; ++c) {
        // need chunks c AND c+1 ready (c+1 ks0 frags pre-loaded this iter)
        if (c < N_CHUNKS - 2) { CP_WAIT(1); } else { CP_WAIT(0); }
        __syncthreads();
        if (c + 3 < N_CHUNKS) { issue(c + 3); CP_COMMIT(); }
        const uint32_t St  = sbase + (uint32_t)(c & (N_STAGE - 1)) * STAGE_B;
        const uint32_t Stn = sbase + (uint32_t)((c + 1) & (N_STAGE - 1)) * STAGE_B;
        if (c == 0) load_frag(St, 0, 0);     // prime once
#pragma unroll
        for (int ks = 0; ks < 4; ks++) {
            if (ks < 3) load_frag(St, ks + 1, (ks + 1) & 1);
            else if (c + 1 < N_CHUNKS) load_frag(Stn, 0, 0);   // roll into next chunk
            mma_frag(ks & 1);
        }
    }

    // ================== fused epilogue: BN+ReLU -> conv2 -> softmax ==========
    __syncthreads();                          // all ldsm done; arena reusable
    float* smf = (float*)smem_raw;
    float* xs  = smf;                         // [128][292]
    float* w2s = smf + W2S_OFF;               // [256][28]  (transposed w2)
    float* b2s = smf + B2S_OFF;               // [25]

    for (int e = t; e < 25 * 256; e += 512) {
        int n = e >> 8, ch = e & 255;
        w2s[ch * 28 + n] = w2[n * 256 + ch];
    }
    if (t < 25) b2s[t] = b2[t];

    // BN + ReLU, stage x1 into xs
#pragma unroll
    for (int ni = 0; ni < 8; ni++) {
        int n0 = wn + (ni >> 1) * 16 + (ni & 1) * 8 + (l & 3) * 2;
        float sc0 = g_scale[n0], sh0 = g_shift[n0];
        float sc1 = g_scale[n0 + 1], sh1 = g_shift[n0 + 1];
#pragma unroll
        for (int mi = 0; mi < 2; mi++)
#pragma unroll
            for (int h = 0; h < 2; h++) {
                int ml = wm + mi * 16 + (l >> 2) + h * 8;
                float v0 = fmaxf(fmaf(acc[mi][ni][h * 2 + 0], sc0, sh0), 0.f);
                float v1 = fmaxf(fmaf(acc[mi][ni][h * 2 + 1], sc1, sh1), 0.f);
                xs[ml * XS_STRIDE + n0] = v0;
                xs[ml * XS_STRIDE + n0 + 1] = v1;
            }
    }
    __syncthreads();

    // channel-quarter partial logits (vectorized): warp w -> pg=w&3, cg=w>>2
    const int pg = w & 3;
    const int cg = w >> 2;
    const int pos = pg * 32 + l;
    float lg[25];
#pragma unroll
    for (int n = 0; n < 25; n++) lg[n] = 0.f;
    {
        const float* xrow = xs + pos * XS_STRIDE + cg * 64;
        const float* wbse = w2s + (cg * 64) * 28;
#pragma unroll 4
        for (int k4 = 0; k4 < 16; k4++) {
            float4 xv4 = *(const float4*)(xrow + k4 * 4);
#pragma unroll
            for (int j = 0; j < 4; j++) {
                float xv = (j == 0) ? xv4.x : (j == 1) ? xv4.y : (j == 2) ? xv4.z : xv4.w;
                const float* wp = wbse + (k4 * 4 + j) * 28;
#pragma unroll
                for (int q = 0; q < 6; q++) {
                    float4 wv = *(const float4*)(wp + q * 4);
                    lg[q * 4 + 0] = fmaf(xv, wv.x, lg[q * 4 + 0]);
                    lg[q * 4 + 1] = fmaf(xv, wv.y, lg[q * 4 + 1]);
                    lg[q * 4 + 2] = fmaf(xv, wv.z, lg[q * 4 + 2]);
                    lg[q * 4 + 3] = fmaf(xv, wv.w, lg[q * 4 + 3]);
                }
                lg[24] = fmaf(xv, wp[24], lg[24]);
            }
        }
    }
    __syncthreads();                          // xs dead -> overlay red

    float* red = smf;                         // [4][128][26]
#pragma unroll
    for (int n = 0; n < 25; n++) red[(cg * 128 + pos) * 26 + n] = lg[n];
    __syncthreads();

    if (t < 128) {
        float v[25];
        float mx = -1e30f;
#pragma unroll
        for (int n = 0; n < 25; n++) {
            v[n] = red[t * 26 + n] + red[(128 + t) * 26 + n]
                 + red[(256 + t) * 26 + n] + red[(384 + t) * 26 + n] + b2s[n];
            mx = fmaxf(mx, v[n]);
        }
        float sum = 0.f;
#pragma unroll
        for (int n = 0; n < 25; n++) { v[n] = __expf(v[n] - mx); sum += v[n]; }
        float inv = 1.f / sum;
        int m = m0 + t;
        int b = m / 576;
        int pb = m - b * 576;
        float* kp = g_kmap + (size_t)b * 14400 + pb;
#pragma unroll
        for (int n = 0; n < 25; n++) kp[(size_t)n * 576] = v[n] * inv;
    }
}

// ---------------- 25-tap propagation (channel-split grid) ----------------
#define CSPLIT 8
#define CPB    32

__global__ __launch_bounds__(192) void prop_kernel(const float* __restrict__ src,
                                                   float* __restrict__ out) {
    __shared__ float patch[2][336];

    const int t = threadIdx.x;
    const int blk = blockIdx.x;
    const int cs = blk & (CSPLIT - 1);
    const int brg = blk >> 3;
    const int b = brg / 3;
    const int rg = brg - b * 3;
    const int pos0 = rg * 192;
    const int y0 = rg * 8;
    const int c0 = cs * CPB;

    float pr[25];
    const float* kp = g_kmap + (size_t)b * 14400 + pos0 + t;
#pragma unroll
    for (int n = 0; n < 25; n++) pr[n] = kp[(size_t)n * 576];

    int off[2];
    bool val[2];
#pragma unroll
    for (int i = 0; i < 2; i++) {
        int e = t + i * 192;
        int ry = e / 28;
        int rx = e - ry * 28;
        int iy = y0 - 2 + ry;
        int ix = rx - 2;
        val[i] = (e < 336) && iy >= 0 && iy < 24 && ix >= 0 && ix < 24;
        off[i] = val[i] ? iy * 24 + ix : 0;
    }

    const float* sb = src + (size_t)b * 147456 + (size_t)c0 * 576;
    const int py = t / 24 + 2;
    const int px = t - (t / 24) * 24 + 2;
    const int pcenter = py * 28 + px;
    float* ob = out + (size_t)b * 147456 + (size_t)c0 * 576 + pos0 + t;

#pragma unroll
    for (int i = 0; i < 2; i++) {
        int e = t + i * 192;
        if (e < 336) patch[0][e] = val[i] ? sb[off[i]] : 0.f;
    }
    __syncthreads();

    for (int c = 0; c < CPB; ++c) {
        float nv[2];
        if (c + 1 < CPB) {
#pragma unroll
            for (int i = 0; i < 2; i++)
                nv[i] = val[i] ? sb[(size_t)(c + 1) * 576 + off[i]] : 0.f;
        }
        const float* pc = &patch[c & 1][0];
        float sum = 0.f;
#pragma unroll
        for (int o = 0; o < 25; o++) {
            int ddy = o / 5 - 2;
            int ddx = o - (o / 5) * 5 - 2;
            sum = fmaf(pc[pcenter + ddy * 28 + ddx], pr[o], sum);
        }
        ob[(size_t)c * 576] = sum;

        if (c + 1 < CPB) {
#pragma unroll
            for (int i = 0; i < 2; i++) {
                int e = t + i * 192;
                if (e < 336) patch[(c + 1) & 1][e] = nv[i];
            }
        }
        __syncthreads();
    }
}

// ---------------- launcher ----------------
extern "C" void kernel_launch(void* const* d_in, const int* in_sizes, int n_in,
                              void* d_out, int out_size) {
    const float* src = (const float*)d_in[0];
    const float* det = (const float*)d_in[1];
    const float* w1  = (const float*)d_in[2];
    const float* b1  = (const float*)d_in[3];
    const float* gam = (const float*)d_in[4];
    const float* bet = (const float*)d_in[5];
    const float* mu  = (const float*)d_in[6];
    const float* var = (const float*)d_in[7];
    const float* w2  = (const float*)d_in[8];
    const float* b2  = (const float*)d_in[9];
    float* out = (float*)d_out;

    cudaFuncSetAttribute(conv1_mma, cudaFuncAttributeMaxDynamicSharedMemorySize, CONV1_SMEM);

    snprep_kernel<<<1, 256>>>(b1, gam, bet, mu, var);
    wprep_kernel<<<(9 * 256 * KPRIME + 255) / 256, 256>>>(w1);
    xprep_kernel<<<128 * 26, 256>>>(src, det);

    conv1_mma<<<576, 512, CONV1_SMEM>>>(w2, b2);   // conv1+BN+ReLU+conv2+softmax

    prop_kernel<<<128 * 3 * CSPLIT, 192>>>(src, out);
}